// round 2
// baseline (speedup 1.0000x reference)
#include <cuda_runtime.h>

// ---------------------------------------------------------------------------
// RNN_32109175505717: 3-layer tanh RNN (B=4096, T=128, HID=64, F=14) + FC head
// Strategy: fully fused kernel, fp32 with packed fma.rn.f32x2 (2 batch
// elements per 64-bit register), all weights resident in shared memory
// duplicated as {w,w} pairs, double-buffered hidden state.
// ---------------------------------------------------------------------------

#define HID        64
#define F_IN       14
#define T_STEPS    128
#define B_TOTAL    4096
#define ELEMS_BLK  32
#define NTHREADS   256
#define NBLOCKS    (B_TOTAL / ELEMS_BLK)   // 128

typedef unsigned long long ull;

// ---- shared memory layout (units: ull = 8 bytes = one f32x2) --------------
#define OFF_WIH0   0                      // 14*64
#define OFF_WHH0   (OFF_WIH0 + 14*64)     // 64*64
#define OFF_WIH1   (OFF_WHH0 + 64*64)
#define OFF_WHH1   (OFF_WIH1 + 64*64)
#define OFF_WIH2   (OFF_WHH1 + 64*64)
#define OFF_WHH2   (OFF_WIH2 + 64*64)
#define OFF_H      (OFF_WHH2 + 64*64)     // 3 layers * 2 bufs * 64k * 16 pairs
#define OFF_XS     (OFF_H + 3*2*64*16)    // 14 * 16 pairs
#define OFF_RED    (OFF_XS + 14*16)       // 256 floats = 128 ull
#define SMEM_ULL   (OFF_RED + 128)
#define SMEM_BYTES (SMEM_ULL * 8)         // 222976 bytes

// ---- f32x2 helpers --------------------------------------------------------
__device__ __forceinline__ ull pack2(float lo, float hi) {
    ull r; asm("mov.b64 %0, {%1, %2};" : "=l"(r) : "f"(lo), "f"(hi)); return r;
}
__device__ __forceinline__ void unpack2(ull v, float& lo, float& hi) {
    asm("mov.b64 {%0, %1}, %2;" : "=f"(lo), "=f"(hi) : "l"(v));
}
__device__ __forceinline__ ull fma2(ull a, ull b, ull c) {
    ull d; asm("fma.rn.f32x2 %0, %1, %2, %3;" : "=l"(d) : "l"(a), "l"(b), "l"(c));
    return d;
}

__device__ __forceinline__ float fast_tanh(float x) {
    x = fminf(fmaxf(x, -12.0f), 12.0f);     // avoid inf/inf
    float e = __expf(x + x);
    return __fdividef(e - 1.0f, e + 1.0f);
}
__device__ __forceinline__ ull tanh2(ull v) {
    float a, b; unpack2(v, a, b);
    return pack2(fast_tanh(a), fast_tanh(b));
}

// ---- core matvec accumulate ----------------------------------------------
// hsrc: packed pairs, stride 16 ull per k.  wsrc: dup pairs, stride 64 per k.
// Thread accumulates a 2j x 4e tile in 4 f32x2 registers.
template<int NK>
__device__ __forceinline__ void mv_acc(const ull* __restrict__ hsrc,
                                       const ull* __restrict__ wsrc,
                                       int et2, int jt2,
                                       ull& a00, ull& a01, ull& a10, ull& a11)
{
#pragma unroll 16
    for (int k = 0; k < NK; ++k) {
        ulonglong2 hv = *reinterpret_cast<const ulonglong2*>(hsrc + k * 16 + et2);
        ulonglong2 wv = *reinterpret_cast<const ulonglong2*>(wsrc + k * 64 + jt2);
        a00 = fma2(hv.x, wv.x, a00);   // {e0,e1} x j0
        a01 = fma2(hv.y, wv.x, a01);   // {e2,e3} x j0
        a10 = fma2(hv.x, wv.y, a10);   // {e0,e1} x j1
        a11 = fma2(hv.y, wv.y, a11);   // {e2,e3} x j1
    }
}

// ---- weight loader: g[j][k] row-major -> smem dup-transposed s[k*64 + j] --
__device__ __forceinline__ void load_wdup(const float* __restrict__ g, ull* s,
                                          int cols /*k-count*/)
{
    int total = HID * cols;
    for (int idx = threadIdx.x; idx < total; idx += NTHREADS) {
        int j = idx / cols;
        int k = idx - j * cols;
        float w = g[idx];
        s[k * HID + j] = pack2(w, w);
    }
}

__global__ void __launch_bounds__(NTHREADS, 1)
rnn_fused_kernel(const float* __restrict__ x,
                 const float* __restrict__ Wih0, const float* __restrict__ Whh0,
                 const float* __restrict__ bih0, const float* __restrict__ bhh0,
                 const float* __restrict__ Wih1, const float* __restrict__ Whh1,
                 const float* __restrict__ bih1, const float* __restrict__ bhh1,
                 const float* __restrict__ Wih2, const float* __restrict__ Whh2,
                 const float* __restrict__ bih2, const float* __restrict__ bhh2,
                 const float* __restrict__ fc1w, const float* __restrict__ fc1b,
                 const float* __restrict__ fc2w, const float* __restrict__ fc2b,
                 float* __restrict__ out)
{
    extern __shared__ ull sm[];

    // ---- stage weights into shared memory (duplicated pairs) ----
    load_wdup(Wih0, sm + OFF_WIH0, F_IN);
    load_wdup(Whh0, sm + OFF_WHH0, HID);
    load_wdup(Wih1, sm + OFF_WIH1, HID);
    load_wdup(Whh1, sm + OFF_WHH1, HID);
    load_wdup(Wih2, sm + OFF_WIH2, HID);
    load_wdup(Whh2, sm + OFF_WHH2, HID);

    // zero hidden-state buffers (both parity buffers, all 3 layers)
    for (int idx = threadIdx.x; idx < 3 * 2 * 64 * 16; idx += NTHREADS)
        sm[OFF_H + idx] = 0ull;

    const int tid = threadIdx.x;
    const int et  = tid & 7;        // e-tile: 4 elems = pairs {2et, 2et+1}
    const int jt  = tid >> 3;       // j-tile: outputs {2jt, 2jt+1}
    const int et2 = et * 2;
    const int jt2 = jt * 2;
    const int j0  = jt2, j1 = jt2 + 1;

    // per-thread duplicated biases (b_ih + b_hh always add together)
    const ull b0j0 = pack2(bih0[j0] + bhh0[j0], bih0[j0] + bhh0[j0]);
    const ull b0j1 = pack2(bih0[j1] + bhh0[j1], bih0[j1] + bhh0[j1]);
    const ull b1j0 = pack2(bih1[j0] + bhh1[j0], bih1[j0] + bhh1[j0]);
    const ull b1j1 = pack2(bih1[j1] + bhh1[j1], bih1[j1] + bhh1[j1]);
    const ull b2j0 = pack2(bih2[j0] + bhh2[j0], bih2[j0] + bhh2[j0]);
    const ull b2j1 = pack2(bih2[j1] + bhh2[j1], bih2[j1] + bhh2[j1]);

    const float* xblk = x + (size_t)blockIdx.x * ELEMS_BLK * T_STEPS * F_IN;
    float* xs_f = (float*)(sm + OFF_XS);    // xs[f][32 elems] fp32 view

    __syncthreads();

    for (int t = 0; t < T_STEPS; ++t) {
        const int Wb = t & 1;
        const int Rb = Wb ^ 1;
        ull* h0R = sm + OFF_H + (0 * 2 + Rb) * 1024;
        ull* h0W = sm + OFF_H + (0 * 2 + Wb) * 1024;
        ull* h1R = sm + OFF_H + (1 * 2 + Rb) * 1024;
        ull* h1W = sm + OFF_H + (1 * 2 + Wb) * 1024;
        ull* h2R = sm + OFF_H + (2 * 2 + Rb) * 1024;
        ull* h2W = sm + OFF_H + (2 * 2 + Wb) * 1024;

        // stage x[:, t, :] for this block's 32 elements: xs[f][e]
        for (int idx = tid; idx < ELEMS_BLK * F_IN; idx += NTHREADS) {
            int e = idx / F_IN;
            int f = idx - e * F_IN;
            xs_f[f * ELEMS_BLK + e] = xblk[e * (T_STEPS * F_IN) + t * F_IN + f];
        }
        __syncthreads();

        // ---- layer 0 ----
        {
            ull a00 = b0j0, a01 = b0j0, a10 = b0j1, a11 = b0j1;
            mv_acc<F_IN>(sm + OFF_XS, sm + OFF_WIH0, et2, jt2, a00, a01, a10, a11);
            mv_acc<HID >(h0R,         sm + OFF_WHH0, et2, jt2, a00, a01, a10, a11);
            ulonglong2 s0; s0.x = tanh2(a00); s0.y = tanh2(a01);
            *reinterpret_cast<ulonglong2*>(h0W + j0 * 16 + et2) = s0;
            ulonglong2 s1; s1.x = tanh2(a10); s1.y = tanh2(a11);
            *reinterpret_cast<ulonglong2*>(h0W + j1 * 16 + et2) = s1;
        }
        __syncthreads();

        // ---- layer 1 ----
        {
            ull a00 = b1j0, a01 = b1j0, a10 = b1j1, a11 = b1j1;
            mv_acc<HID>(h0W, sm + OFF_WIH1, et2, jt2, a00, a01, a10, a11);
            mv_acc<HID>(h1R, sm + OFF_WHH1, et2, jt2, a00, a01, a10, a11);
            ulonglong2 s0; s0.x = tanh2(a00); s0.y = tanh2(a01);
            *reinterpret_cast<ulonglong2*>(h1W + j0 * 16 + et2) = s0;
            ulonglong2 s1; s1.x = tanh2(a10); s1.y = tanh2(a11);
            *reinterpret_cast<ulonglong2*>(h1W + j1 * 16 + et2) = s1;
        }
        __syncthreads();

        // ---- layer 2 ----
        {
            ull a00 = b2j0, a01 = b2j0, a10 = b2j1, a11 = b2j1;
            mv_acc<HID>(h1W, sm + OFF_WIH2, et2, jt2, a00, a01, a10, a11);
            mv_acc<HID>(h2R, sm + OFF_WHH2, et2, jt2, a00, a01, a10, a11);
            ulonglong2 s0; s0.x = tanh2(a00); s0.y = tanh2(a01);
            *reinterpret_cast<ulonglong2*>(h2W + j0 * 16 + et2) = s0;
            ulonglong2 s1; s1.x = tanh2(a10); s1.y = tanh2(a11);
            *reinterpret_cast<ulonglong2*>(h2W + j1 * 16 + et2) = s1;
        }
        // no barrier needed here: next-iteration barrier (after x staging)
        // separates these stores from their consumers (layer 2 of t+1),
        // and xs writers are separated from layer-0 readers by the
        // layer-0 barrier of step t.
    }
    __syncthreads();

    // ---- FC head on final h2 (t=127 wrote parity buffer 1) ----
    const float* h2f = (const float*)(sm + OFF_H + (2 * 2 + 1) * 1024); // [k][32]
    {
        int e  = tid >> 3;         // 0..31  element within block
        int mg = tid & 7;          // 0..7   group of 4 fc1 units
        float contrib = 0.0f;
#pragma unroll
        for (int mi = 0; mi < 4; ++mi) {
            int m = mg * 4 + mi;
            float s = fc1b[m];
#pragma unroll 16
            for (int k = 0; k < HID; ++k)
                s = fmaf(fc1w[m * HID + k], h2f[k * 32 + e], s);
            contrib = fmaf(fc2w[m], fmaxf(s, 0.0f), contrib);
        }
        float* red = (float*)(sm + OFF_RED);
        red[tid] = contrib;        // red[e*8 + mg]
    }
    __syncthreads();
    if (tid < ELEMS_BLK) {
        float* red = (float*)(sm + OFF_RED);
        float s = fc2b[0];
#pragma unroll
        for (int i = 0; i < 8; ++i) s += red[tid * 8 + i];
        out[blockIdx.x * ELEMS_BLK + tid] = s;
    }
}

extern "C" void kernel_launch(void* const* d_in, const int* in_sizes, int n_in,
                              void* d_out, int out_size)
{
    const float* x    = (const float*)d_in[0];
    const float* Wih0 = (const float*)d_in[1];
    const float* Whh0 = (const float*)d_in[2];
    const float* bih0 = (const float*)d_in[3];
    const float* bhh0 = (const float*)d_in[4];
    const float* Wih1 = (const float*)d_in[5];
    const float* Whh1 = (const float*)d_in[6];
    const float* bih1 = (const float*)d_in[7];
    const float* bhh1 = (const float*)d_in[8];
    const float* Wih2 = (const float*)d_in[9];
    const float* Whh2 = (const float*)d_in[10];
    const float* bih2 = (const float*)d_in[11];
    const float* bhh2 = (const float*)d_in[12];
    const float* fc1w = (const float*)d_in[13];
    const float* fc1b = (const float*)d_in[14];
    const float* fc2w = (const float*)d_in[15];
    const float* fc2b = (const float*)d_in[16];
    float* out = (float*)d_out;

    cudaFuncSetAttribute(rnn_fused_kernel,
                         cudaFuncAttributeMaxDynamicSharedMemorySize, SMEM_BYTES);

    rnn_fused_kernel<<<NBLOCKS, NTHREADS, SMEM_BYTES>>>(
        x, Wih0, Whh0, bih0, bhh0,
        Wih1, Whh1, bih1, bhh1,
        Wih2, Whh2, bih2, bhh2,
        fc1w, fc1b, fc2w, fc2b, out);
}